// round 2
// baseline (speedup 1.0000x reference)
#include <cuda_runtime.h>

#define TPB 256
#define NBLK 2048

// Scratch accumulators (device globals — no allocation allowed).
// g_sums: [0]=class_sum, [1]=bbox_sum, [2]=sigma_sum, [3]=neg_sum, [4]=n_pos
__device__ double g_sums[5];
__device__ int    g_last_pos;

__global__ void rpn_zero_kernel() {
    int t = threadIdx.x;
    if (t < 5) g_sums[t] = 0.0;
    if (t == 5) g_last_pos = -1;
}

__inline__ __device__ double warp_sum(double v) {
    #pragma unroll
    for (int o = 16; o > 0; o >>= 1) v += __shfl_down_sync(0xffffffffu, v, o);
    return v;
}
__inline__ __device__ int warp_sum_i(int v) {
    #pragma unroll
    for (int o = 16; o > 0; o >>= 1) v += __shfl_down_sync(0xffffffffu, v, o);
    return v;
}
__inline__ __device__ int warp_max_i(int v) {
    #pragma unroll
    for (int o = 16; o > 0; o >>= 1) v = max(v, __shfl_down_sync(0xffffffffu, v, o));
    return v;
}

__global__ void rpn_reduce_kernel(const float4* __restrict__ bbox,   // [4M]
                                  const float2* __restrict__ logits, // [4M]
                                  const float4* __restrict__ sigma,  // [4M]
                                  const float4* __restrict__ gt,     // [4M]
                                  const int* __restrict__ label,     // [4M] i32
                                  const int* __restrict__ vidx,      // [V] i32
                                  int V) {
    const float EPS = 1e-10f;
    double acc_c = 0.0, acc_b = 0.0, acc_s = 0.0, acc_n = 0.0;
    int npos = 0;
    int lastp = -1;

    for (int i = blockIdx.x * blockDim.x + threadIdx.x; i < V;
         i += gridDim.x * blockDim.x) {
        int a = vidx[i];
        int lbl = label[a];
        float2 lg = logits[a];
        float4 p = bbox[a];
        float4 t = gt[a];
        float4 s = sigma[a];

        // Classification: -log_softmax at label (numerically stable 2-class LSE)
        float m  = fmaxf(lg.x, lg.y);
        float d  = -fabsf(lg.x - lg.y);
        float lse = m + log1pf(expf(d));
        float sel = (lbl == 1) ? lg.y : lg.x;
        acc_c += (double)(lse - sel);

        float dx = p.x - t.x, dy = p.y - t.y, dz = p.z - t.z, dw = p.w - t.w;
        float sq0 = 0.5f * dx * dx, sq1 = 0.5f * dy * dy,
              sq2 = 0.5f * dz * dz, sq3 = 0.5f * dw * dw;
        float e0 = EPS + s.x, e1 = EPS + s.y, e2 = EPS + s.z, e3 = EPS + s.w;
        float i0 = 1.0f / e0, i1 = 1.0f / e1, i2 = 1.0f / e2, i3 = 1.0f / e3;

        if (lbl == 1) {
            acc_b += (double)(sq0 * i0 + sq1 * i1 + sq2 * i2 + sq3 * i3);
            acc_s += (double)(0.5f * (logf(e0) + logf(e1) + logf(e2) + logf(e3)));
            npos++;
            lastp = i;
        } else {
            acc_n += (double)(i0 + i1 + i2 + i3);
        }
    }

    // Block reduction: warp shuffle -> shared -> warp 0 -> atomics
    __shared__ double sh[4][TPB / 32];
    __shared__ int shi[2][TPB / 32];
    int lane = threadIdx.x & 31;
    int wid  = threadIdx.x >> 5;

    acc_c = warp_sum(acc_c);
    acc_b = warp_sum(acc_b);
    acc_s = warp_sum(acc_s);
    acc_n = warp_sum(acc_n);
    npos  = warp_sum_i(npos);
    lastp = warp_max_i(lastp);
    if (lane == 0) {
        sh[0][wid] = acc_c; sh[1][wid] = acc_b;
        sh[2][wid] = acc_s; sh[3][wid] = acc_n;
        shi[0][wid] = npos; shi[1][wid] = lastp;
    }
    __syncthreads();
    if (wid == 0) {
        const int NW = TPB / 32;
        double c = (lane < NW) ? sh[0][lane] : 0.0;
        double b = (lane < NW) ? sh[1][lane] : 0.0;
        double s2 = (lane < NW) ? sh[2][lane] : 0.0;
        double n2 = (lane < NW) ? sh[3][lane] : 0.0;
        int np = (lane < NW) ? shi[0][lane] : 0;
        int lp = (lane < NW) ? shi[1][lane] : -1;
        c = warp_sum(c); b = warp_sum(b); s2 = warp_sum(s2); n2 = warp_sum(n2);
        np = warp_sum_i(np); lp = warp_max_i(lp);
        if (lane == 0) {
            atomicAdd(&g_sums[0], c);
            atomicAdd(&g_sums[1], b);
            atomicAdd(&g_sums[2], s2);
            atomicAdd(&g_sums[3], n2);
            atomicAdd(&g_sums[4], (double)np);
            atomicMax(&g_last_pos, lp);
        }
    }
}

__global__ void rpn_finalize_kernel(const float4* __restrict__ bbox,
                                    const float4* __restrict__ gt,
                                    const int* __restrict__ vidx,
                                    float* __restrict__ out, int V) {
    if (threadIdx.x == 0 && blockIdx.x == 0) {
        double npos = g_sums[4];
        double nneg = (double)V - npos;
        out[0] = (float)(g_sums[0] / (double)V);
        out[1] = (float)(g_sums[1] / npos);
        out[2] = (float)(g_sums[2] / npos);
        out[3] = (float)(g_sums[3] / nneg);
        int lp = g_last_pos;
        float sq = 0.0f;
        if (lp >= 0) {
            int a = vidx[lp];
            float4 p = bbox[a];
            float4 t = gt[a];
            float dx = p.x - t.x, dy = p.y - t.y, dz = p.z - t.z, dw = p.w - t.w;
            sq = 0.5f * (dx * dx + dy * dy + dz * dz + dw * dw);
        }
        out[4] = (float)((double)sq / npos);
    }
}

extern "C" void kernel_launch(void* const* d_in, const int* in_sizes, int n_in,
                              void* d_out, int out_size) {
    const float4* bbox   = (const float4*)d_in[0];  // [1,4M,4] f32
    const float2* logits = (const float2*)d_in[1];  // [1,4M,2] f32
    const float4* sigma  = (const float4*)d_in[2];  // [1,4M,4] f32
    const float4* gt     = (const float4*)d_in[3];  // [1,4M,4] f32
    const int*    label  = (const int*)d_in[4];     // [1,4M] i32 (JAX x64 off)
    const int*    vidx   = (const int*)d_in[5];     // [V] i32
    float* out = (float*)d_out;
    int V = in_sizes[5];

    rpn_zero_kernel<<<1, 32>>>();
    int blocks = (V + TPB - 1) / TPB;
    if (blocks > NBLK) blocks = NBLK;
    rpn_reduce_kernel<<<blocks, TPB>>>(bbox, logits, sigma, gt, label, vidx, V);
    rpn_finalize_kernel<<<1, 32>>>(bbox, gt, vidx, out, V);
}